// round 3
// baseline (speedup 1.0000x reference)
#include <cuda_runtime.h>
#include <math.h>

#define BB 16
#define TT 12
#define NN 300
#define DD 64
#define TW 10
#define NWIN (BB*TW)
#define NBT  (BB*TT)
#define K1_BLOCKS (NBT*3)

__device__ float g_wf [NBT*NN*DD];
__device__ float g_Mtp[K1_BLOCKS*DD*DD];
__device__ float g_ksp[K1_BLOCKS*DD];
__device__ float g_MW [NWIN*DD*DD];
__device__ float g_ksw[NWIN*DD];

// k1: per (b,t,chunk of 100 rows): store wf, accumulate partial M and ksum
__global__ void __launch_bounds__(256) k1(const float* __restrict__ feat,
                                          const float* __restrict__ weights) {
    __shared__ float sv[100*DD];
    __shared__ float snrm[100];
    __shared__ float gws[DD];
    const int tid = threadIdx.x, bid = blockIdx.x;
    const int bt = bid / 3, chunk = bid - bt*3;
    const int base = (bt*NN + chunk*100) * DD;

    if (tid < DD) gws[tid] = 1.0f / (1.0f + expf(-weights[tid]));
    for (int idx = tid; idx < 100*DD; idx += 256) sv[idx] = feat[base + idx];
    __syncthreads();

    {   // per-row inverse norm of gated vector; write wf
        const int wid = tid >> 5, lane = tid & 31;
        for (int r = wid; r < 100; r += 8) {
            float e0 = sv[r*DD + lane], e1 = sv[r*DD + 32 + lane];
            float g0 = gws[lane]*e0, g1 = gws[lane+32]*e1;
            float ss = g0*g0 + g1*g1;
            #pragma unroll
            for (int o = 16; o; o >>= 1) ss += __shfl_xor_sync(0xffffffffu, ss, o);
            float inv = 1.0f / fmaxf(sqrtf(ss), 1e-12f);
            if (lane == 0) snrm[r] = inv;
            g_wf[base + r*DD + lane]      = g0*inv;
            g_wf[base + r*DD + 32 + lane] = g1*inv;
        }
    }
    __syncthreads();

    const int tx = tid & 15, ty = tid >> 4;
    const float4* sv4 = (const float4*)sv;
    float acc[4][4]; float ksa[4] = {0.f,0.f,0.f,0.f};
    #pragma unroll
    for (int a=0;a<4;a++)
        #pragma unroll
        for (int b=0;b<4;b++) acc[a][b] = 0.f;

    for (int r = 0; r < 100; r++) {
        float s = snrm[r];
        float4 vi = sv4[r*16 + tx];
        float4 vj = sv4[r*16 + ty];
        float wv[4]  = { s*vi.x, s*vi.y, s*vi.z, s*vi.w };
        float vjv[4] = { vj.x, vj.y, vj.z, vj.w };
        #pragma unroll
        for (int a=0;a<4;a++)
            #pragma unroll
            for (int b=0;b<4;b++) acc[a][b] += wv[a]*vjv[b];
        if (ty == 0) { ksa[0]+=wv[0]; ksa[1]+=wv[1]; ksa[2]+=wv[2]; ksa[3]+=wv[3]; }
    }
    const int i0 = tx*4, j0 = ty*4;
    float* Mout = g_Mtp + bid*DD*DD;
    #pragma unroll
    for (int a=0;a<4;a++) {
        float gwa = gws[i0+a];
        #pragma unroll
        for (int b=0;b<4;b++) Mout[(i0+a)*DD + j0+b] = gwa*acc[a][b];
    }
    if (ty == 0) {
        #pragma unroll
        for (int c=0;c<4;c++) g_ksp[bid*DD + i0+c] = gws[i0+c]*ksa[c];
    }
}

// k1b: per window: M = sum of 9 partials; MW = M@w1; ksw = sum of partial ksums
__global__ void __launch_bounds__(256) k1b(const float* __restrict__ w1) {
    __shared__ float Ms[DD*DD];
    __shared__ float w1s[DD*DD];
    const int tid = threadIdx.x, w = blockIdx.x;
    const int b = w / TW, t2 = w - b*TW;
    const int bt0 = b*TT + t2;

    for (int idx = tid; idx < DD*DD; idx += 256) {
        float s = 0.f;
        #pragma unroll
        for (int dt=0; dt<3; dt++)
            #pragma unroll
            for (int c=0; c<3; c++) s += g_Mtp[((bt0+dt)*3 + c)*DD*DD + idx];
        Ms[idx] = s;
        w1s[idx] = w1[idx];
    }
    if (tid < DD) {
        float s = 0.f;
        #pragma unroll
        for (int dt=0; dt<3; dt++)
            #pragma unroll
            for (int c=0; c<3; c++) s += g_ksp[((bt0+dt)*3 + c)*DD + tid];
        g_ksw[w*DD + tid] = s;
    }
    __syncthreads();

    const int tx = tid & 15, ty = tid >> 4;
    const int i0 = ty*4, j0 = tx*4;
    float acc[4][4];
    #pragma unroll
    for (int a=0;a<4;a++)
        #pragma unroll
        for (int b2=0;b2<4;b2++) acc[a][b2] = 0.f;
    for (int k = 0; k < DD; k++) {
        float av[4], bv[4];
        #pragma unroll
        for (int a=0;a<4;a++) av[a] = Ms[(i0+a)*DD + k];
        #pragma unroll
        for (int b2=0;b2<4;b2++) bv[b2] = w1s[k*DD + j0+b2];
        #pragma unroll
        for (int a=0;a<4;a++)
            #pragma unroll
            for (int b2=0;b2<4;b2++) acc[a][b2] += av[a]*bv[b2];
    }
    float* MWo = g_MW + w*DD*DD;
    #pragma unroll
    for (int a=0;a<4;a++)
        #pragma unroll
        for (int b2=0;b2<4;b2++) MWo[(i0+a)*DD + j0+b2] = acc[a][b2];
}

// k2: one thread per output row. h1=relu(dinv*q@MW+b1); out=LN(feat + h1@w2+b2)
extern __shared__ float s_dyn[];
__global__ void __launch_bounds__(128) k2(const float* __restrict__ feat,
                                          const float* __restrict__ b1,
                                          const float* __restrict__ w2,
                                          const float* __restrict__ b2,
                                          const float* __restrict__ gamma,
                                          const float* __restrict__ beta,
                                          float* __restrict__ out) {
    float* sMW = s_dyn;            // 4096
    float* sW2 = sMW + 4096;       // 4096
    float* sQ  = sW2 + 4096;       // 100*65
    float* sKs = sQ + 100*65;      // 64
    float* sB1 = sKs + 64;
    float* sB2 = sB1 + 64;
    float* sGa = sB2 + 64;
    float* sBe = sGa + 64;

    const int tid = threadIdx.x, bid = blockIdx.x;
    const int w = bid / 3, chunk = bid - w*3;
    const int b = w / TW, t2 = w - b*TW;
    const int tile = b*TT + t2 + 2;           // timestep t2+2
    const int rowbase = (tile*NN + chunk*100) * DD;

    for (int idx = tid; idx < 4096; idx += 128) {
        sMW[idx] = g_MW[w*4096 + idx];
        sW2[idx] = w2[idx];
    }
    for (int idx = tid; idx < 100*DD; idx += 128)
        sQ[(idx >> 6)*65 + (idx & 63)] = g_wf[rowbase + idx];
    if (tid < 64) {
        sKs[tid] = g_ksw[w*DD + tid];
        sB1[tid] = b1[tid]; sB2[tid] = b2[tid];
        sGa[tid] = gamma[tid]; sBe[tid] = beta[tid];
    }
    __syncthreads();

    if (tid < 100) {
        float* myq = sQ + tid*65;
        float deg = 0.f;
        #pragma unroll 16
        for (int i = 0; i < DD; i++) deg += myq[i]*sKs[i];
        float dinv = (deg == 0.f) ? 0.f : 1.f/deg;

        float acc[DD];
        #pragma unroll
        for (int j = 0; j < DD; j++) acc[j] = 0.f;
        for (int i = 0; i < DD; i++) {
            float qi = myq[i];
            #pragma unroll
            for (int j = 0; j < DD; j++) acc[j] += qi*sMW[i*DD + j];
        }
        #pragma unroll
        for (int j = 0; j < DD; j++) myq[j] = fmaxf(acc[j]*dinv + sB1[j], 0.f);

        #pragma unroll
        for (int j = 0; j < DD; j++) acc[j] = 0.f;
        for (int i = 0; i < DD; i++) {
            float hi = myq[i];
            #pragma unroll
            for (int j = 0; j < DD; j++) acc[j] += hi*sW2[i*DD + j];
        }

        const float4* frow = (const float4*)(feat + rowbase + tid*DD);
        #pragma unroll
        for (int j4 = 0; j4 < 16; j4++) {
            float4 f = frow[j4];
            acc[4*j4+0] += sB2[4*j4+0] + f.x;
            acc[4*j4+1] += sB2[4*j4+1] + f.y;
            acc[4*j4+2] += sB2[4*j4+2] + f.z;
            acc[4*j4+3] += sB2[4*j4+3] + f.w;
        }
        float mu = 0.f;
        #pragma unroll
        for (int j = 0; j < DD; j++) mu += acc[j];
        mu *= (1.f/DD);
        float var = 0.f;
        #pragma unroll
        for (int j = 0; j < DD; j++) { float d = acc[j]-mu; var += d*d; }
        var *= (1.f/DD);
        float rs = rsqrtf(var + 1e-5f);
        #pragma unroll
        for (int j = 0; j < DD; j++) myq[j] = (acc[j]-mu)*rs*sGa[j] + sBe[j];
    }
    __syncthreads();

    const int outbase = (w*NN + chunk*100) * DD;
    for (int idx = tid; idx < 100*DD; idx += 128)
        out[outbase + idx] = sQ[(idx >> 6)*65 + (idx & 63)];
}

extern "C" void kernel_launch(void* const* d_in, const int* in_sizes, int n_in,
                              void* d_out, int out_size) {
    const float* feat    = (const float*)d_in[0];
    const float* weights = (const float*)d_in[1];
    const float* w1      = (const float*)d_in[2];
    const float* b1      = (const float*)d_in[3];
    const float* w2      = (const float*)d_in[4];
    const float* b2      = (const float*)d_in[5];
    const float* gamma   = (const float*)d_in[6];
    const float* beta    = (const float*)d_in[7];
    float* out = (float*)d_out;

    static bool attr_set = false;
    size_t smem = (4096 + 4096 + 100*65 + 5*64) * sizeof(float);
    if (!attr_set) {
        cudaFuncSetAttribute(k2, cudaFuncAttributeMaxDynamicSharedMemorySize, (int)smem);
        attr_set = true;
    }
    k1 <<<K1_BLOCKS, 256>>>(feat, weights);
    k1b<<<NWIN, 256>>>(w1);
    k2 <<<NWIN*3, 128, smem>>>(feat, b1, w2, b2, gamma, beta, out);
}